// round 16
// baseline (speedup 1.0000x reference)
#include <cuda_runtime.h>
#include <cstdint>

#define BB    16
#define HWSZ  65536
#define NPIX  (BB * HWSZ)
#define NACC  16
#define THR   128
#define TPX   256                  // pixels per tile (2 per thread)
#define TILES 8
#define BPX   (TPX * TILES)        // 2048 px per block
#define NBLK  (NPIX / BPX)         // 512 blocks (32 per image)
#define TBUF  (TPX * 10)           // floats per stream buffer (10KB)

// ---------------- device-global scratch (zero-initialized at load) ---------
__device__ float  g_masked[NPIX];    // slow path only
__device__ float  g_clsloss[NPIX];   // slow path only
__device__ double g_acc[5][NACC];    // 0:Sw(ce*w) 1:L1num 2:L1den 3:L0num 4:L0den
__device__ double g_negsum[BB];      // per-batch sum of cls-ce over negatives
__device__ int    g_npos[BB];
__device__ int    g_nneg[BB];
__device__ unsigned g_done;

__device__ __forceinline__ float comp2(const float2 v, int q) { return q ? v.y : v.x; }

// ---------------- single fused, pipelined kernel (2 px/thread) --------------
__global__ __launch_bounds__(THR) void k_fused(const float* __restrict__ target,
                                               const float* __restrict__ logits,
                                               float* __restrict__ out) {
    __shared__ __align__(16) float s_tg[2][TBUF];   // AoS target tiles (10KB)
    __shared__ __align__(16) float s_lg[2][TBUF];   // ch-major logits tiles
    __shared__ float  shr[6][4];
    __shared__ int    shc[4];
    __shared__ int    s_last;

    const int tid = threadIdx.x;
    const int blk = blockIdx.x;
    const int b   = blk >> 5;              // 32 blocks per batch image
    const int i0  = blk * BPX;
    const int hw0 = (blk & 31) * BPX;
    const int w = tid >> 5, lane = tid & 31;
    const unsigned full = 0xFFFFFFFFu;

    // L2 evict_last: keep the replay-invariant inputs resident in L2
    uint64_t pol;
    asm("createpolicy.fractional.L2::evict_last.b64 %0, 1.0;" : "=l"(pol));

    const float4* tg4  = (const float4*)(target + (size_t)i0 * 10);  // 640 f4/tile
    const float4* lgf4 = (const float4*)(logits + (size_t)b * 10 * HWSZ + hw0);

    const unsigned stg_base = (unsigned)__cvta_generic_to_shared(s_tg);
    const unsigned slg_base = (unsigned)__cvta_generic_to_shared(s_lg);

    // ---- stage tile t into buffer buf (5+5 float4 per thread) --------------
    auto stage = [&](int t, int buf) {
        const float4* src_t = tg4 + t * (TBUF / 4);
        const unsigned dst_t = stg_base + (unsigned)buf * (TBUF * 4);
#pragma unroll
        for (int k = 0; k < 5; k++) {                  // target: 640 float4
            const int j = tid + THR * k;
            asm volatile(
                "cp.async.cg.shared.global.L2::cache_hint [%0], [%1], 16, %2;\n"
                :: "r"(dst_t + (unsigned)j * 16), "l"(src_t + j), "l"(pol));
        }
        const unsigned dst_l = slg_base + (unsigned)buf * (TBUF * 4);
#pragma unroll
        for (int k = 0; k < 5; k++) {                  // logits: 10ch x 64 float4
            const int j = tid + THR * k;
            const int c = j >> 6, e = j & 63;
            asm volatile(
                "cp.async.cg.shared.global.L2::cache_hint [%0], [%1], 16, %2;\n"
                :: "r"(dst_l + (unsigned)j * 16),
                   "l"(lgf4 + c * (HWSZ / 4) + t * (TPX / 4) + e), "l"(pol));
        }
        asm volatile("cp.async.commit_group;\n");
    };

    float sw = 0.f, l1n = 0.f, l1d = 0.f, l0n = 0.f, l0d = 0.f, ns = 0.f;
    int cnts = 0;                          // cpos + (cneg << 16)

    stage(0, 0);   // prologue

#pragma unroll
    for (int t = 0; t < TILES; t++) {
        if (t < TILES - 1) {
            stage(t + 1, (t + 1) & 1);
            asm volatile("cp.async.wait_group 1;\n");
        } else {
            asm volatile("cp.async.wait_group 0;\n");
        }
        __syncthreads();

        const int buf = t & 1;
        // target: 2 pixels = 80B per thread = 5 LDS.128, conflict-free
        const float4* tp4 = (const float4*)(&s_tg[buf][0] + tid * 20);
        float4 tt[5];
#pragma unroll
        for (int k = 0; k < 5; k++) tt[k] = tp4[k];
        const float* tv = (const float*)tt;       // tv[10q + f]
        // logits: float2 per channel (pixels 2tid, 2tid+1)
        const float2* zl2 = (const float2*)&s_lg[buf][0];
        float2 z2[10];
#pragma unroll
        for (int c = 0; c < 10; c++) z2[c] = zl2[c * (TPX / 2) + tid];

#pragma unroll
        for (int q = 0; q < 2; q++) {
            const float lab = tv[10 * q + 0];
            const float wt  = tv[10 * q + 1];
            const bool pos = lab > 0.0f;
            const bool neg = lab == 0.0f;
            cnts += (int)pos + ((int)neg << 16);

            const float z0 = comp2(z2[0], q);
            const float z1 = comp2(z2[1], q);
            const float e  = __expf(-fabsf(z1 - z0));
            const float ce = __logf(1.0f + e) + fmaxf(z0, z1) - (pos ? z1 : z0);
            sw += ce * wt;
            if (neg) ns += ce;

#pragma unroll
            for (int n = 0; n < 4; n++) {
                const float a  = comp2(z2[2 + n], q);
                const float c  = comp2(z2[6 + n], q);
                const bool  li = tv[10 * q + 2 + n] != 0.0f;
                const float lw = tv[10 * q + 6 + n];
                const float ee  = __expf(-fabsf(c - a));
                const float lce = __logf(1.0f + ee) + fmaxf(a, c) - (li ? c : a);
                if (li) { l1n += lce * lw; l1d += lw; }
                else    { l0n += lce * lw; l0d += lw; }
            }
        }
        __syncthreads();   // protect buf from overwrite by stage(t+2)
    }

    // -------- block reduction: 6 floats + 1 packed int ----------------------
    float v0 = sw, v1 = l1n, v2 = l1d, v3 = l0n, v4 = l0d, v5 = ns;
    int ic = cnts;
#pragma unroll
    for (int off = 16; off; off >>= 1) {
        v0 += __shfl_down_sync(full, v0, off);
        v1 += __shfl_down_sync(full, v1, off);
        v2 += __shfl_down_sync(full, v2, off);
        v3 += __shfl_down_sync(full, v3, off);
        v4 += __shfl_down_sync(full, v4, off);
        v5 += __shfl_down_sync(full, v5, off);
        ic += __shfl_down_sync(full, ic, off);
    }
    if (lane == 0) {
        shr[0][w] = v0; shr[1][w] = v1; shr[2][w] = v2;
        shr[3][w] = v3; shr[4][w] = v4; shr[5][w] = v5;
        shc[w] = ic;
    }
    __syncthreads();

    if (tid == 0) {
        float t0 = 0, t1 = 0, t2 = 0, t3 = 0, t4 = 0, t5 = 0;
        int c = 0;
#pragma unroll
        for (int j = 0; j < 4; j++) {
            t0 += shr[0][j]; t1 += shr[1][j]; t2 += shr[2][j];
            t3 += shr[3][j]; t4 += shr[4][j]; t5 += shr[5][j];
            c += shc[j];
        }
        const int slot = blk & (NACC - 1);
        atomicAdd(&g_acc[0][slot], (double)t0);
        atomicAdd(&g_acc[1][slot], (double)t1);
        atomicAdd(&g_acc[2][slot], (double)t2);
        atomicAdd(&g_acc[3][slot], (double)t3);
        atomicAdd(&g_acc[4][slot], (double)t4);
        atomicAdd(&g_negsum[b], (double)t5);
        atomicAdd(&g_npos[b], c & 0xFFFF);
        atomicAdd(&g_nneg[b], c >> 16);
        __threadfence();
        const unsigned prev = atomicAdd(&g_done, 1u);
        s_last = (prev == NBLK - 1);
    }
    __syncthreads();
    if (!s_last) return;

    // =================== tail: last block only ===============================
    __threadfence();
    __shared__ double   sels[BB];
    __shared__ long long nsels[BB];
    __shared__ unsigned s_slowmask;
    __shared__ int      hist[256];
    __shared__ unsigned s_pref;
    __shared__ int      s_k;
    __shared__ float    ssum[4];
    __shared__ int      scnt[4];

    if (tid == 0) s_slowmask = 0u;
    __syncthreads();

    if (tid < BB) {
        const int np = __ldcg(&g_npos[tid]);
        const int nn = __ldcg(&g_nneg[tid]);
        long long k = 3ll * np; if ((long long)nn < k) k = nn;
        if (np == 0 || k == 0 || k == (long long)nn) {
            sels[tid]  = __ldcg(&g_negsum[tid]);    // selected == all negatives
            nsels[tid] = nn;
        } else {
            sels[tid] = 0.0; nsels[tid] = 0;
            atomicOr(&s_slowmask, 1u << tid);
        }
    }
    __syncthreads();

    // generic slow path (0 < k < nneg): recompute scores, radix-select, sum.
    unsigned slow = s_slowmask;
    while (slow) {
        const int bb = __ffs(slow) - 1;
        slow &= slow - 1;
        const int np = __ldcg(&g_npos[bb]);
        const int nn = __ldcg(&g_nneg[bb]);
        long long k = 3ll * np; if ((long long)nn < k) k = nn;

        float* sc = g_masked  + ((size_t)bb << 16);
        float* cl = g_clsloss + ((size_t)bb << 16);
        const float* lgz0 = logits + (size_t)bb * 10 * HWSZ;
        const float* lgz1 = lgz0 + HWSZ;
        const float* tgl  = target + (size_t)bb * HWSZ * 10;

        for (int j = tid; j < HWSZ; j += THR) {
            const float lab = tgl[(size_t)j * 10];
            const bool pos = lab > 0.0f;
            const bool neg = lab == 0.0f;
            const float z0 = lgz0[j];
            const float z1 = lgz1[j];
            const float d  = z1 - z0;
            const float e  = __expf(-fabsf(d));
            const float ce = __logf(1.0f + e) + fmaxf(z0, z1) - (pos ? z1 : z0);
            const float r  = __fdividef(1.0f, 1.0f + e);
            const float score = (d > 0.0f) ? e * r : r;   // softmax p0
            sc[j] = neg ? score : __uint_as_float(0x7f800000u);
            cl[j] = ce;
        }
        __syncthreads();

        if (tid == 0) { s_pref = 0u; s_k = (int)k; }
        __syncthreads();
        for (int shift = 24; shift >= 0; shift -= 8) {
            hist[tid] = 0; hist[tid + 128] = 0;
            __syncthreads();
            const unsigned pref = s_pref;
            const unsigned mask = (shift == 24) ? 0u : (0xFFFFFFFFu << (shift + 8));
            for (int j = tid; j < HWSZ; j += THR) {
                const unsigned u = __float_as_uint(sc[j]);
                if ((u & mask) == pref) atomicAdd(&hist[(u >> shift) & 0xFFu], 1);
            }
            __syncthreads();
            if (tid == 0) {
                int kk = s_k, cum = 0; unsigned dd = 255;
                for (int v = 0; v < 256; v++) {
                    const int h = hist[v];
                    if (cum + h >= kk) { dd = (unsigned)v; s_k = kk - cum; break; }
                    cum += h;
                }
                s_pref = pref | (dd << shift);
            }
            __syncthreads();
        }
        const float thr = __uint_as_float(s_pref);
        float sum = 0.f; int cnt = 0;
        for (int j = tid; j < HWSZ; j += THR) {
            const float m = sc[j];
            if (m <= thr) { sum += cl[j]; cnt++; }
        }
#pragma unroll
        for (int off = 16; off; off >>= 1) {
            sum += __shfl_down_sync(full, sum, off);
            cnt += __shfl_down_sync(full, cnt, off);
        }
        if (lane == 0) { ssum[w] = sum; scnt[w] = cnt; }
        __syncthreads();
        if (tid == 0) {
            float t = 0; int c = 0;
#pragma unroll
            for (int j = 0; j < 4; j++) { t += ssum[j]; c += scnt[j]; }
            sels[bb] = (double)t; nsels[bb] = c;
        }
        __syncthreads();
    }

    // -------- finalize (warp 0) ---------------------------------------------
    if (tid < 32) {
        double a[5];
#pragma unroll
        for (int r = 0; r < 5; r++) {
            double v = (lane < NACC) ? __ldcg(&g_acc[r][lane]) : 0.0;
#pragma unroll
            for (int off = 16; off; off >>= 1) v += __shfl_down_sync(full, v, off);
            a[r] = v;
        }
        int np = (lane < BB) ? __ldcg(&g_npos[lane]) : 0;
        double ss = (lane < BB) ? sels[lane] : 0.0;
        long long nsl = (lane < BB) ? nsels[lane] : 0ll;
#pragma unroll
        for (int off = 16; off; off >>= 1) {
            np  += __shfl_down_sync(full, np, off);
            ss  += __shfl_down_sync(full, ss, off);
            nsl += __shfl_down_sync(full, nsl, off);
        }
        if (lane == 0) {
            const double cls = (a[0] + ss) / ((double)np + (double)nsl);
            double link = 0.0;
            if (np > 0) {
                const double l1 = (a[2] != 0.0) ? a[1] / a[2] : 0.0;
                const double l0 = (a[4] != 0.0) ? a[3] / a[4] : 0.0;
                link = l1 + l0;
            }
            out[0] = (float)(cls * 2.0);
            out[1] = (float)link;
        }
    }
    __syncthreads();

    // -------- reset global state for next graph replay ----------------------
    if (tid < 5 * NACC) ((double*)g_acc)[tid] = 0.0;              // 0..79
    if (tid >= 80 && tid < 80 + BB) g_negsum[tid - 80] = 0.0;     // 80..95
    if (tid >= 96 && tid < 96 + BB) { g_npos[tid - 96] = 0; g_nneg[tid - 96] = 0; }
    if (tid == 112) g_done = 0u;
}

// ---------------- launcher ----------------------------------------------------
extern "C" void kernel_launch(void* const* d_in, const int* in_sizes, int n_in,
                              void* d_out, int out_size) {
    const float* target = (const float*)d_in[0];
    const float* logits = (const float*)d_in[1];
    float* out = (float*)d_out;

    k_fused<<<NBLK, THR>>>(target, logits, out);
}

// round 17
// speedup vs baseline: 1.0152x; 1.0152x over previous
#include <cuda_runtime.h>
#include <cstdint>

#define BB    16
#define HWSZ  65536
#define NPIX  (BB * HWSZ)
#define NACC  16
#define THR   256
#define TPX   512                  // pixels per tile (2 per thread)
#define TILES 4
#define BPX   (TPX * TILES)        // 2048 px per block
#define NBLK  (NPIX / BPX)         // 512 blocks (32 per image)
#define TBUF  (TPX * 10)           // target floats per buffer (20KB)

// ---------------- device-global scratch (zero-initialized at load) ---------
__device__ float  g_masked[NPIX];    // slow path only
__device__ float  g_clsloss[NPIX];   // slow path only
__device__ double g_acc[5][NACC];    // 0:Sw(ce*w) 1:L1num 2:L1den 3:L0num 4:L0den
__device__ double g_negsum[BB];      // per-batch sum of cls-ce over negatives
__device__ int    g_npos[BB];
__device__ int    g_nneg[BB];
__device__ unsigned g_done;

__device__ __forceinline__ float comp2(const float2 v, int q) { return q ? v.y : v.x; }

// ---------------- single fused kernel: cp.async target + LDG logits ---------
__global__ __launch_bounds__(THR) void k_fused(const float* __restrict__ target,
                                               const float* __restrict__ logits,
                                               float* __restrict__ out) {
    __shared__ __align__(16) float s_tg[2][TBUF];   // AoS target tiles (20KB each)
    __shared__ float  shr[6][8];
    __shared__ int    shc[8];
    __shared__ int    s_last;

    const int tid = threadIdx.x;
    const int blk = blockIdx.x;
    const int b   = blk >> 5;              // 32 blocks per batch image
    const int i0  = blk * BPX;
    const int hw0 = (blk & 31) * BPX;
    const int w = tid >> 5, lane = tid & 31;
    const unsigned full = 0xFFFFFFFFu;

    // L2 evict_last: keep the replay-invariant inputs resident in L2
    uint64_t pol;
    asm("createpolicy.fractional.L2::evict_last.b64 %0, 1.0;" : "=l"(pol));

    const float4* tg4  = (const float4*)(target + (size_t)i0 * 10);  // 1280 f4/tile
    const float2* lgf2 = (const float2*)(logits + (size_t)b * 10 * HWSZ + hw0);

    const unsigned stg_base = (unsigned)__cvta_generic_to_shared(s_tg);

    // ---- stage target tile t into buffer buf (5 float4 per thread) ---------
    auto stage = [&](int t, int buf) {
        const float4* src_t = tg4 + t * (TBUF / 4);
        const unsigned dst_t = stg_base + (unsigned)buf * (TBUF * 4);
#pragma unroll
        for (int k = 0; k < 5; k++) {                  // 1280 float4
            const int j = tid + THR * k;
            asm volatile(
                "cp.async.cg.shared.global.L2::cache_hint [%0], [%1], 16, %2;\n"
                :: "r"(dst_t + (unsigned)j * 16), "l"(src_t + j), "l"(pol));
        }
        asm volatile("cp.async.commit_group;\n");
    };

    float sw = 0.f, l1n = 0.f, l1d = 0.f, l0n = 0.f, l0d = 0.f, ns = 0.f;
    int cnts = 0;                          // cpos + (cneg << 16)

    stage(0, 0);   // prologue

#pragma unroll
    for (int t = 0; t < TILES; t++) {
        if (t < TILES - 1) stage(t + 1, (t + 1) & 1);

        // logits for tile t: direct coalesced LDG.64 (evict_last), overlaps
        // the cp.async wait below
        float2 z2[10];
#pragma unroll
        for (int c = 0; c < 10; c++) {
            const float2* p = lgf2 + c * (HWSZ / 2) + t * (TPX / 2) + tid;
            asm("ld.global.L2::cache_hint.v2.f32 {%0, %1}, [%2], %3;"
                : "=f"(z2[c].x), "=f"(z2[c].y) : "l"(p), "l"(pol));
        }

        if (t < TILES - 1) asm volatile("cp.async.wait_group 1;\n");
        else               asm volatile("cp.async.wait_group 0;\n");
        __syncthreads();

        const int buf = t & 1;
        // target: 2 pixels = 80B per thread = 5 LDS.128 (conflict-free)
        const float4* tp4 = (const float4*)(&s_tg[buf][0] + tid * 20);
        float4 tt[5];
#pragma unroll
        for (int k = 0; k < 5; k++) tt[k] = tp4[k];
        const float* tv = (const float*)tt;       // tv[10q + f]

#pragma unroll
        for (int q = 0; q < 2; q++) {
            const float lab = tv[10 * q + 0];
            const float wt  = tv[10 * q + 1];
            const bool pos = lab > 0.0f;
            const bool neg = lab == 0.0f;
            cnts += (int)pos + ((int)neg << 16);

            const float z0 = comp2(z2[0], q);
            const float z1 = comp2(z2[1], q);
            const float e  = __expf(-fabsf(z1 - z0));
            const float ce = __logf(1.0f + e) + fmaxf(z0, z1) - (pos ? z1 : z0);
            sw += ce * wt;
            if (neg) ns += ce;

#pragma unroll
            for (int n = 0; n < 4; n++) {
                const float a  = comp2(z2[2 + n], q);
                const float c  = comp2(z2[6 + n], q);
                const bool  li = tv[10 * q + 2 + n] != 0.0f;
                const float lw = tv[10 * q + 6 + n];
                const float ee  = __expf(-fabsf(c - a));
                const float lce = __logf(1.0f + ee) + fmaxf(a, c) - (li ? c : a);
                if (li) { l1n += lce * lw; l1d += lw; }
                else    { l0n += lce * lw; l0d += lw; }
            }
        }
        __syncthreads();   // protect buf from overwrite by stage(t+2)
    }

    // -------- block reduction: 6 floats + 1 packed int ----------------------
    float v0 = sw, v1 = l1n, v2 = l1d, v3 = l0n, v4 = l0d, v5 = ns;
    int ic = cnts;
#pragma unroll
    for (int off = 16; off; off >>= 1) {
        v0 += __shfl_down_sync(full, v0, off);
        v1 += __shfl_down_sync(full, v1, off);
        v2 += __shfl_down_sync(full, v2, off);
        v3 += __shfl_down_sync(full, v3, off);
        v4 += __shfl_down_sync(full, v4, off);
        v5 += __shfl_down_sync(full, v5, off);
        ic += __shfl_down_sync(full, ic, off);
    }
    if (lane == 0) {
        shr[0][w] = v0; shr[1][w] = v1; shr[2][w] = v2;
        shr[3][w] = v3; shr[4][w] = v4; shr[5][w] = v5;
        shc[w] = ic;
    }
    __syncthreads();

    if (tid == 0) {
        float t0 = 0, t1 = 0, t2 = 0, t3 = 0, t4 = 0, t5 = 0;
        int c = 0;
#pragma unroll
        for (int j = 0; j < 8; j++) {
            t0 += shr[0][j]; t1 += shr[1][j]; t2 += shr[2][j];
            t3 += shr[3][j]; t4 += shr[4][j]; t5 += shr[5][j];
            c += shc[j];
        }
        const int slot = blk & (NACC - 1);
        atomicAdd(&g_acc[0][slot], (double)t0);
        atomicAdd(&g_acc[1][slot], (double)t1);
        atomicAdd(&g_acc[2][slot], (double)t2);
        atomicAdd(&g_acc[3][slot], (double)t3);
        atomicAdd(&g_acc[4][slot], (double)t4);
        atomicAdd(&g_negsum[b], (double)t5);
        atomicAdd(&g_npos[b], c & 0xFFFF);
        atomicAdd(&g_nneg[b], c >> 16);
        __threadfence();
        const unsigned prev = atomicAdd(&g_done, 1u);
        s_last = (prev == NBLK - 1);
    }
    __syncthreads();
    if (!s_last) return;

    // =================== tail: last block only ===============================
    __threadfence();
    __shared__ double   sels[BB];
    __shared__ long long nsels[BB];
    __shared__ unsigned s_slowmask;
    __shared__ int      hist[256];
    __shared__ unsigned s_pref;
    __shared__ int      s_k;
    __shared__ float    ssum[8];
    __shared__ int      scnt[8];

    if (tid == 0) s_slowmask = 0u;
    __syncthreads();

    if (tid < BB) {
        const int np = __ldcg(&g_npos[tid]);
        const int nn = __ldcg(&g_nneg[tid]);
        long long k = 3ll * np; if ((long long)nn < k) k = nn;
        if (np == 0 || k == 0 || k == (long long)nn) {
            sels[tid]  = __ldcg(&g_negsum[tid]);    // selected == all negatives
            nsels[tid] = nn;
        } else {
            sels[tid] = 0.0; nsels[tid] = 0;
            atomicOr(&s_slowmask, 1u << tid);
        }
    }
    __syncthreads();

    // generic slow path (0 < k < nneg): recompute scores, radix-select, sum.
    unsigned slow = s_slowmask;
    while (slow) {
        const int bb = __ffs(slow) - 1;
        slow &= slow - 1;
        const int np = __ldcg(&g_npos[bb]);
        const int nn = __ldcg(&g_nneg[bb]);
        long long k = 3ll * np; if ((long long)nn < k) k = nn;

        float* sc = g_masked  + ((size_t)bb << 16);
        float* cl = g_clsloss + ((size_t)bb << 16);
        const float* lgz0 = logits + (size_t)bb * 10 * HWSZ;
        const float* lgz1 = lgz0 + HWSZ;
        const float* tgl  = target + (size_t)bb * HWSZ * 10;

        for (int j = tid; j < HWSZ; j += THR) {
            const float lab = tgl[(size_t)j * 10];
            const bool pos = lab > 0.0f;
            const bool neg = lab == 0.0f;
            const float z0 = lgz0[j];
            const float z1 = lgz1[j];
            const float d  = z1 - z0;
            const float e  = __expf(-fabsf(d));
            const float ce = __logf(1.0f + e) + fmaxf(z0, z1) - (pos ? z1 : z0);
            const float r  = __fdividef(1.0f, 1.0f + e);
            const float score = (d > 0.0f) ? e * r : r;   // softmax p0
            sc[j] = neg ? score : __uint_as_float(0x7f800000u);
            cl[j] = ce;
        }
        __syncthreads();

        if (tid == 0) { s_pref = 0u; s_k = (int)k; }
        __syncthreads();
        for (int shift = 24; shift >= 0; shift -= 8) {
            hist[tid & 255] = 0;
            __syncthreads();
            const unsigned pref = s_pref;
            const unsigned mask = (shift == 24) ? 0u : (0xFFFFFFFFu << (shift + 8));
            for (int j = tid; j < HWSZ; j += THR) {
                const unsigned u = __float_as_uint(sc[j]);
                if ((u & mask) == pref) atomicAdd(&hist[(u >> shift) & 0xFFu], 1);
            }
            __syncthreads();
            if (tid == 0) {
                int kk = s_k, cum = 0; unsigned dd = 255;
                for (int v = 0; v < 256; v++) {
                    const int h = hist[v];
                    if (cum + h >= kk) { dd = (unsigned)v; s_k = kk - cum; break; }
                    cum += h;
                }
                s_pref = pref | (dd << shift);
            }
            __syncthreads();
        }
        const float thr = __uint_as_float(s_pref);
        float sum = 0.f; int cnt = 0;
        for (int j = tid; j < HWSZ; j += THR) {
            const float m = sc[j];
            if (m <= thr) { sum += cl[j]; cnt++; }
        }
#pragma unroll
        for (int off = 16; off; off >>= 1) {
            sum += __shfl_down_sync(full, sum, off);
            cnt += __shfl_down_sync(full, cnt, off);
        }
        if (lane == 0) { ssum[w] = sum; scnt[w] = cnt; }
        __syncthreads();
        if (tid == 0) {
            float t = 0; int c = 0;
#pragma unroll
            for (int j = 0; j < 8; j++) { t += ssum[j]; c += scnt[j]; }
            sels[bb] = (double)t; nsels[bb] = c;
        }
        __syncthreads();
    }

    // -------- finalize (warp 0) ---------------------------------------------
    if (tid < 32) {
        double a[5];
#pragma unroll
        for (int r = 0; r < 5; r++) {
            double v = (lane < NACC) ? __ldcg(&g_acc[r][lane]) : 0.0;
#pragma unroll
            for (int off = 16; off; off >>= 1) v += __shfl_down_sync(full, v, off);
            a[r] = v;
        }
        int np = (lane < BB) ? __ldcg(&g_npos[lane]) : 0;
        double ss = (lane < BB) ? sels[lane] : 0.0;
        long long nsl = (lane < BB) ? nsels[lane] : 0ll;
#pragma unroll
        for (int off = 16; off; off >>= 1) {
            np  += __shfl_down_sync(full, np, off);
            ss  += __shfl_down_sync(full, ss, off);
            nsl += __shfl_down_sync(full, nsl, off);
        }
        if (lane == 0) {
            const double cls = (a[0] + ss) / ((double)np + (double)nsl);
            double link = 0.0;
            if (np > 0) {
                const double l1 = (a[2] != 0.0) ? a[1] / a[2] : 0.0;
                const double l0 = (a[4] != 0.0) ? a[3] / a[4] : 0.0;
                link = l1 + l0;
            }
            out[0] = (float)(cls * 2.0);
            out[1] = (float)link;
        }
    }
    __syncthreads();

    // -------- reset global state for next graph replay ----------------------
    if (tid < 5 * NACC) ((double*)g_acc)[tid] = 0.0;              // 0..79
    if (tid >= 80 && tid < 80 + BB) g_negsum[tid - 80] = 0.0;     // 80..95
    if (tid >= 96 && tid < 96 + BB) { g_npos[tid - 96] = 0; g_nneg[tid - 96] = 0; }
    if (tid == 112) g_done = 0u;
}

// ---------------- launcher ----------------------------------------------------
extern "C" void kernel_launch(void* const* d_in, const int* in_sizes, int n_in,
                              void* d_out, int out_size) {
    const float* target = (const float*)d_in[0];
    const float* logits = (const float*)d_in[1];
    float* out = (float*)d_out;

    k_fused<<<NBLK, THR>>>(target, logits, out);
}